// round 3
// baseline (speedup 1.0000x reference)
#include <cuda_runtime.h>

// Problem constants (fixed by reference_code)
#define LSEQ 8192
#define BATCH 32
#define CIN 7
#define KER 73            // 512 // 7
#define DM 512
#define RT 8              // output rows per tile
#define HALF 128          // rows handled by each thread-half
#define SL 256            // rows per block strip
#define TPH (HALF / RT)   // 16 tiles per half
#define WROWS (SL + 17)   // 273 window rows: strip + 16 back + 1 fwd
#define NV 10             // smem variants: 7 same-channel dup + 3 straddle pairs

typedef unsigned long long u64;

// Packed fp32x2 FMA (Blackwell): one issue slot, two FMAs.
__device__ __forceinline__ u64 fma2(u64 a, u64 b, u64 c) {
    u64 d;
    asm("fma.rn.f32x2 %0, %1, %2, %3;" : "=l"(d) : "l"(a), "l"(b), "l"(c));
    return d;
}
__device__ __forceinline__ u64 pack2(float lo, float hi) {
    u64 d;
    asm("mov.b64 %0, {%1, %2};" : "=l"(d) : "f"(lo), "f"(hi));
    return d;
}

// out[b, n, c*73+k] = conv_b[k] + sum_{j=0..17} W2[k][j] * x[b, n+1-j, c]
//   W2[k][j] = conv_w[k][ (j/3)*3 + (2 - j%3) ]
// Valid only where conv position p = n-1+t (after circular wrap) >= 15.
// Thread layout: tid = (h<<8) | u. Pair u covers channels d0=2u, d1=2u+1;
// half h covers rows [s0 + h*128, +128) in 16 tiles of 8 rows.

__global__ __launch_bounds__(512, 2)
void tokemb_kernel(const float* __restrict__ x,
                   const float* __restrict__ conv_w,
                   const float* __restrict__ conv_b,
                   const float* __restrict__ left_w,
                   const float* __restrict__ left_b,
                   float* __restrict__ out)
{
    const int tid = threadIdx.x;
    const int u   = tid & 255;        // channel pair index
    const int h   = tid >> 8;         // row half
    const int s0  = blockIdx.x * SL;  // strip start row
    const int b   = blockIdx.y;

    const int d0 = 2 * u, d1 = 2 * u + 1;
    const int c0 = d0 / KER;
    const int c1 = (d1 == DM - 1) ? (CIN - 1) : (d1 / KER);
    // smem variant: same-channel dup (0..6) or straddle pair (7..9)
    const int v  = (c0 == c1) ? c0 : (7 + (c0 >> 1));

    const bool m1 = (d1 < CIN * KER);                 // lane1 main vs rem
    const float* w0 = conv_w + (d0 % KER) * 18;       // d0 <= 510 is always main
    const float* w1 = m1 ? (conv_w + (d1 % KER) * 18) : left_w;
    const float fb0 = conv_b[d0 % KER];
    const float fb1 = m1 ? conv_b[d1 % KER] : left_b[0];
    const u64 bias2 = pack2(fb0, fb1);

    // Packed, offset-ordered weights: wp[j] multiplies x[n+1-j] on both lanes.
    u64 wp[18];
    #pragma unroll
    for (int j = 0; j < 18; ++j) {
        const int src = (j / 3) * 3 + 2 - (j % 3);
        wp[j] = pack2(w0[src], w1[src]);
    }

    const float* xb = x + (size_t)b * LSEQ * CIN;

    // Stage window rows [s0-16, s0+256] as pre-packed 64-bit pairs, NV variants
    // per row. Clamped rows are only consumed by slow-path tiles (ignored there).
    __shared__ u64 xp[WROWS * NV];
    for (int idx = tid; idx < WROWS * NV; idx += 512) {
        const int r  = idx / NV;
        const int vv = idx - r * NV;
        int g = s0 - 16 + r;
        g = min(max(g, 0), LSEQ - 1);
        const int lo = (vv < 7) ? vv : 2 * (vv - 7);
        const int hi = (vv < 7) ? vv : lo + 1;
        xp[idx] = pack2(xb[g * CIN + lo], xb[g * CIN + hi]);
    }
    __syncthreads();

    float* outbase = out + ((size_t)(b * LSEQ + s0 + h * HALF)) * DM + d0;

    #pragma unroll 1
    for (int t = 0; t < TPH; ++t) {
        const int n0 = s0 + h * HALF + t * RT;
        float* op = outbase + t * RT * DM;
        const bool fast = (n0 >= 16) && (n0 + RT <= LSEQ - 1);

        if (fast) {
            // window row i (i=0..24) = x[n0-16+i]; local smem row = h*128+t*8+i
            const u64* xcol = xp + (h * HALF + t * RT) * NV + v;

            u64 acc[RT];
            #pragma unroll
            for (int nl = 0; nl < RT; ++nl) acc[nl] = bias2;

            #pragma unroll
            for (int i = 0; i < RT + 17; ++i) {
                const u64 xv = xcol[i * NV];     // LDS.64, both lanes ready
                #pragma unroll
                for (int j = 0; j < 18; ++j) {
                    const int nl = i + j - 17;   // output row fed by (i, j)
                    if (nl >= 0 && nl < RT)
                        acc[nl] = fma2(wp[j], xv, acc[nl]);
                }
            }

            #pragma unroll
            for (int nl = 0; nl < RT; ++nl)
                *(u64*)(op + nl * DM) = acc[nl];   // STG.64: (d0, d1) contiguous
        } else {
            // Generic path: explicit wrap + validity per conv tap. Only the two
            // first tiles of the sequence and the last one land here.
            for (int nl = 0; nl < RT; ++nl) {
                const int n = n0 + nl;
                float a0 = fb0, a1 = fb1;
                #pragma unroll
                for (int tt = 0; tt < 3; ++tt) {
                    int p = n - 1 + tt;
                    if (p < 0)     p += LSEQ;   // circular pad left
                    if (p >= LSEQ) p -= LSEQ;   // circular pad right
                    if (p >= 15) {              // delay-embedding validity
                        #pragma unroll
                        for (int m = 0; m < 6; ++m) {
                            const int row = (p - 3 * m) * CIN;
                            a0 = fmaf(w0[3 * m + tt], xb[row + c0], a0);
                            a1 = fmaf(w1[3 * m + tt], xb[row + c1], a1);
                        }
                    }
                }
                *(u64*)(op + nl * DM) = pack2(a0, a1);
            }
        }
    }
}

extern "C" void kernel_launch(void* const* d_in, const int* in_sizes, int n_in,
                              void* d_out, int out_size)
{
    const float* x      = (const float*)d_in[0];
    const float* conv_w = (const float*)d_in[1];
    const float* conv_b = (const float*)d_in[2];
    const float* left_w = (const float*)d_in[3];
    const float* left_b = (const float*)d_in[4];
    float* out = (float*)d_out;

    dim3 grid(LSEQ / SL, BATCH);   // (32, 32) = 1024 blocks
    tokemb_kernel<<<grid, 512>>>(x, conv_w, conv_b, left_w, left_b, out);
}